// round 3
// baseline (speedup 1.0000x reference)
#include <cuda_runtime.h>
#include <math.h>

#define BATCH 64
#define NOBJ  16
#define NCLS  7
#define HWDIM 108
#define H1    52
#define OC1   32
#define H2    24
#define OC2   64
#define NFC   36864      // OC2 * H2 * H2
#define NJ    512
#define NSPLIT 64        // one conv2 channel (576 k) per split
#define EPSV  1e-5f

typedef unsigned long long u64;

__device__ __forceinline__ void fma2(u64& d, u64 a, u64 b) {
    asm("fma.rn.f32x2 %0, %1, %2, %0;" : "+l"(d) : "l"(a), "l"(b));
}
__device__ __forceinline__ u64 dup2(float v) {
    u64 d; asm("mov.b64 %0, {%1, %1};" : "=l"(d) : "f"(v)); return d;
}
__device__ __forceinline__ float2 unpk(u64 v) {
    float2 r; asm("mov.b64 {%0, %1}, %2;" : "=f"(r.x), "=f"(r.y) : "l"(v)); return r;
}

// ---------------- scratch (device globals; no allocation) ----------------
__device__ float g_layout[BATCH * NCLS * HWDIM * HWDIM];
__device__ float g_conv1 [BATCH * OC1 * H1 * H1];
__device__ float g_conv2 [BATCH * OC2 * H2 * H2];
__device__ float g_part  [NSPLIT * BATCH * NJ];    // 8 MB
__device__ float g_ybuf  [BATCH * NJ];
__device__ float g_s1p[8][OC1], g_q1p[8][OC1];
__device__ float g_s2p[8][OC2], g_q2p[8][OC2];
__device__ float g_w1t[NCLS * 25 * OC1];   // [ic*25+k][oc]
__device__ float g_w2t[OC1 * 25 * OC2];    // [ic*25+k][oc]

// ---------------- weight transpose prep (merged) ----------------
__global__ void k_wt(const float* __restrict__ w1, const float* __restrict__ w2) {
    int i = blockIdx.x * 256 + threadIdx.x;
    if (i < NCLS * 25 * OC1) {
        int kic = i / OC1, oc = i % OC1;
        g_w1t[i] = w1[oc * 175 + kic];
    }
    int j = i - NCLS * 25 * OC1;
    if (j >= 0 && j < OC1 * 25 * OC2) {
        int kic = j / OC2, oc = j % OC2;
        g_w2t[j] = w2[oc * 800 + kic];
    }
}

// ---------------- K1: layout_bbox + transpose to NCHW ----------------
__global__ void k_layout(const float* __restrict__ image) {
    __shared__ float sx1[NOBJ], sx2[NOBJ], sy1[NOBJ], sy2[NOBJ];
    __shared__ float scls[NOBJ][NCLS];
    const int b = blockIdx.y;
    const int t = threadIdx.x;
    if (t < NOBJ) {
        const float* p = image + (b * NOBJ + t) * (4 + NCLS);
        float xc = p[0] * 108.f, yc = p[1] * 108.f;
        float w  = p[2] * 108.f, h  = p[3] * 108.f;
        sx1[t] = xc - 0.5f * w; sx2[t] = xc + 0.5f * w;
        sy1[t] = yc - 0.5f * h; sy2[t] = yc + 0.5f * h;
        #pragma unroll
        for (int c = 0; c < NCLS; c++) scls[t][c] = p[4 + c];
    }
    __syncthreads();
    const int pix = blockIdx.x * 256 + t;
    if (pix >= HWDIM * HWDIM) return;
    const int hh = pix / HWDIM, ww = pix % HWDIM;
    const float yt = (float)hh, xt = (float)ww;
    float acc[NCLS];
    #pragma unroll
    for (int c = 0; c < NCLS; c++) acc[c] = -1e30f;
    for (int o = 0; o < NOBJ; o++) {
        float x1d = xt - sx1[o], x2d = sx2[o] - xt;
        float y1d = yt - sy1[o], y2d = sy2[o] - yt;
        float yband = fminf(fmaxf(y1d, 0.f), 1.f) * fminf(fmaxf(y2d, 0.f), 1.f);
        float xband = fminf(fmaxf(x1d, 0.f), 1.f) * fminf(fmaxf(x2d, 0.f), 1.f);
        float l1 = fmaxf(1.f - fabsf(x1d), 0.f) * yband;
        float l2 = fmaxf(1.f - fabsf(x2d), 0.f) * yband;
        float l3 = fmaxf(1.f - fabsf(y1d), 0.f) * xband;
        float l4 = fmaxf(1.f - fabsf(y2d), 0.f) * xband;
        float m = fmaxf(fmaxf(l1, l2), fmaxf(l3, l4));
        #pragma unroll
        for (int c = 0; c < NCLS; c++) acc[c] = fmaxf(acc[c], m * scls[o][c]);
    }
    #pragma unroll
    for (int c = 0; c < NCLS; c++)
        g_layout[((b * NCLS + c) * HWDIM + hh) * HWDIM + ww] = acc[c];
}

// ---------------- K2: conv1 7->32, 5x5 stride 2, f32x2 via register packing ----------------
// block: (xtile 0..4, ytile 0..6, b). out tile 8 rows x 12 cols, all 32 oc. 256 threads.
// thread: 4 oc (2 pairs) x 3 consecutive ow.
__global__ void __launch_bounds__(256, 4) k_conv1(const float* __restrict__ bias) {
    __shared__ float xs[NCLS][19][28];
    __shared__ __align__(16) float ws[175 * OC1];
    const int b   = blockIdx.z;
    const int oh0 = blockIdx.y * 8;
    const int ow0 = blockIdx.x * 12;
    const int t   = threadIdx.x;

    for (int i = t; i < NCLS * 19 * 28; i += 256) {
        int ic  = i / (19 * 28);
        int rem = i % (19 * 28);
        int rr = rem / 28, cc = rem % 28;
        int row = 2 * oh0 + rr, col = 2 * ow0 + cc;
        float v = 0.f;
        if (cc < 27 && row < HWDIM && col < HWDIM)
            v = g_layout[((b * NCLS + ic) * HWDIM + row) * HWDIM + col];
        xs[ic][rr][cc] = v;
    }
    for (int i = t; i < 175 * OC1 / 4; i += 256)
        ((float4*)ws)[i] = ((const float4*)g_w1t)[i];
    __syncthreads();

    const int oc0 = (t & 7) * 4;
    const int pg  = t >> 3;          // 0..31
    const int r   = pg >> 2;         // 0..7
    const int c0  = (pg & 3) * 3;    // 0,3,6,9

    u64 acc[2][3];
    #pragma unroll
    for (int q = 0; q < 2; q++)
        #pragma unroll
        for (int p = 0; p < 3; p++) acc[q][p] = 0ull;

    for (int ic = 0; ic < NCLS; ic++) {
        #pragma unroll
        for (int ky = 0; ky < 5; ky++) {
            const float* xr = &xs[ic][2 * r + ky][2 * c0];
            u64 xe[5];
            #pragma unroll
            for (int m = 0; m < 5; m++) xe[m] = dup2(xr[2 * m]);
            #pragma unroll
            for (int kh = 0; kh < 3; kh++) {          // kx = 0,2,4
                ulonglong2 wq = *(const ulonglong2*)&ws[(ic * 25 + ky * 5 + 2 * kh) * OC1 + oc0];
                #pragma unroll
                for (int p = 0; p < 3; p++) {
                    fma2(acc[0][p], wq.x, xe[kh + p]);
                    fma2(acc[1][p], wq.y, xe[kh + p]);
                }
            }
            u64 xo[4];
            #pragma unroll
            for (int m = 0; m < 4; m++) xo[m] = dup2(xr[2 * m + 1]);
            #pragma unroll
            for (int kh = 0; kh < 2; kh++) {          // kx = 1,3
                ulonglong2 wq = *(const ulonglong2*)&ws[(ic * 25 + ky * 5 + 2 * kh + 1) * OC1 + oc0];
                #pragma unroll
                for (int p = 0; p < 3; p++) {
                    fma2(acc[0][p], wq.x, xo[kh + p]);
                    fma2(acc[1][p], wq.y, xo[kh + p]);
                }
            }
        }
    }
    const int oh = oh0 + r;
    if (oh < H1) {
        #pragma unroll
        for (int q = 0; q < 2; q++) {
            float ba = bias[oc0 + 2 * q], bb = bias[oc0 + 2 * q + 1];
            #pragma unroll
            for (int p = 0; p < 3; p++) {
                int ow = ow0 + c0 + p;
                if (ow < H1) {
                    float2 v = unpk(acc[q][p]);
                    g_conv1[((b * OC1 + oc0 + 2 * q)     * H1 + oh) * H1 + ow] = v.x + ba;
                    g_conv1[((b * OC1 + oc0 + 2 * q + 1) * H1 + oh) * H1 + ow] = v.y + bb;
                }
            }
        }
    }
}

// ---------------- K3/K5: two-stage deterministic per-channel sum/sumsq ----------------
__global__ void k_red1() {
    const int c = blockIdx.x, bg = blockIdx.y, t = threadIdx.x;
    float s = 0.f, ss = 0.f;
    for (int i = t; i < 8 * 676; i += 256) {
        int b = bg * 8 + i / 676;
        float4 v = *(const float4*)&g_conv1[(b * OC1 + c) * 2704 + (i % 676) * 4];
        s  += (v.x + v.y) + (v.z + v.w);
        ss += (v.x * v.x + v.y * v.y) + (v.z * v.z + v.w * v.w);
    }
    __shared__ float rs[256], rq[256];
    rs[t] = s; rq[t] = ss;
    __syncthreads();
    for (int off = 128; off > 0; off >>= 1) {
        if (t < off) { rs[t] += rs[t + off]; rq[t] += rq[t + off]; }
        __syncthreads();
    }
    if (t == 0) { g_s1p[bg][c] = rs[0]; g_q1p[bg][c] = rq[0]; }
}

__global__ void k_red2() {
    const int c = blockIdx.x, bg = blockIdx.y, t = threadIdx.x;
    float s = 0.f, ss = 0.f;
    for (int i = t; i < 8 * 144; i += 256) {
        int b = bg * 8 + i / 144;
        float4 v = *(const float4*)&g_conv2[(b * OC2 + c) * 576 + (i % 144) * 4];
        s  += (v.x + v.y) + (v.z + v.w);
        ss += (v.x * v.x + v.y * v.y) + (v.z * v.z + v.w * v.w);
    }
    __shared__ float rs[256], rq[256];
    rs[t] = s; rq[t] = ss;
    __syncthreads();
    for (int off = 128; off > 0; off >>= 1) {
        if (t < off) { rs[t] += rs[t + off]; rq[t] += rq[t + off]; }
        __syncthreads();
    }
    if (t == 0) { g_s2p[bg][c] = rs[0]; g_q2p[bg][c] = rq[0]; }
}

// ---------------- K4: bn1+leaky fused into conv2 32->64, register-packed f32x2 ----------------
// block: (xtile 0..2, ytile 0..2, b). out tile 8x8, 64 oc, 4-ic stages. 256 threads.
// thread: 4 oc (2 pairs) x 4 consecutive ow.
__global__ void __launch_bounds__(256, 4) k_conv2(const float* __restrict__ bias,
                        const float* __restrict__ g1, const float* __restrict__ b1) {
    __shared__ float xs[4][19][20];
    __shared__ __align__(16) float ws[100 * OC2];
    __shared__ float sc1[OC1], sh1[OC1];
    const int b   = blockIdx.z;
    const int oh0 = blockIdx.y * 8;
    const int ow0 = blockIdx.x * 8;
    const int t   = threadIdx.x;

    if (t < OC1) {
        float s = 0.f, q = 0.f;
        #pragma unroll
        for (int i = 0; i < 8; i++) { s += g_s1p[i][t]; q += g_q1p[i][t]; }
        float n = (float)(BATCH * H1 * H1);
        float m = s / n;
        float v = q / n - m * m;
        float sc = rsqrtf(v + EPSV) * g1[t];
        sc1[t] = sc; sh1[t] = b1[t] - m * sc;
    }

    const int oc0 = (t & 15) * 4;
    const int pg  = t >> 4;          // 0..15
    const int r   = pg >> 1;         // 0..7
    const int c0  = (pg & 1) * 4;    // 0 or 4

    u64 acc[2][4];
    #pragma unroll
    for (int q = 0; q < 2; q++)
        #pragma unroll
        for (int p = 0; p < 4; p++) acc[q][p] = 0ull;

    for (int icb = 0; icb < OC1; icb += 4) {
        __syncthreads();
        for (int i = t; i < 4 * 19 * 19; i += 256) {
            int i2  = i / 361;
            int rem = i % 361;
            int rr = rem / 19, cc = rem % 19;
            int ic = icb + i2;
            float v = g_conv1[((b * OC1 + ic) * H1 + 2 * oh0 + rr) * H1 + 2 * ow0 + cc];
            v = v * sc1[ic] + sh1[ic];
            v = v > 0.f ? v : 0.2f * v;
            xs[i2][rr][cc] = v;
        }
        const float4* src = (const float4*)(g_w2t + icb * 25 * OC2);
        for (int i = t; i < 100 * OC2 / 4; i += 256)
            ((float4*)ws)[i] = src[i];
        __syncthreads();

        #pragma unroll
        for (int i2 = 0; i2 < 4; i2++) {
            #pragma unroll
            for (int ky = 0; ky < 5; ky++) {
                const float* xr = &xs[i2][2 * r + ky][2 * c0];
                u64 xe[6];
                #pragma unroll
                for (int m = 0; m < 6; m++) xe[m] = dup2(xr[2 * m]);
                #pragma unroll
                for (int kh = 0; kh < 3; kh++) {      // kx = 0,2,4
                    ulonglong2 wq = *(const ulonglong2*)&ws[(i2 * 25 + ky * 5 + 2 * kh) * OC2 + oc0];
                    #pragma unroll
                    for (int p = 0; p < 4; p++) {
                        fma2(acc[0][p], wq.x, xe[kh + p]);
                        fma2(acc[1][p], wq.y, xe[kh + p]);
                    }
                }
                u64 xo[5];
                #pragma unroll
                for (int m = 0; m < 5; m++) xo[m] = dup2(xr[2 * m + 1]);
                #pragma unroll
                for (int kh = 0; kh < 2; kh++) {      // kx = 1,3
                    ulonglong2 wq = *(const ulonglong2*)&ws[(i2 * 25 + ky * 5 + 2 * kh + 1) * OC2 + oc0];
                    #pragma unroll
                    for (int p = 0; p < 4; p++) {
                        fma2(acc[0][p], wq.x, xo[kh + p]);
                        fma2(acc[1][p], wq.y, xo[kh + p]);
                    }
                }
            }
        }
    }
    const int oh = oh0 + r;
    #pragma unroll
    for (int q = 0; q < 2; q++) {
        float ba = bias[oc0 + 2 * q], bb = bias[oc0 + 2 * q + 1];
        #pragma unroll
        for (int p = 0; p < 4; p++) {
            int ow = ow0 + c0 + p;
            float2 v = unpk(acc[q][p]);
            g_conv2[((b * OC2 + oc0 + 2 * q)     * H2 + oh) * H2 + ow] = v.x + ba;
            g_conv2[((b * OC2 + oc0 + 2 * q + 1) * H2 + oh) * H2 + ow] = v.y + bb;
        }
    }
}

// ---------------- K6: fc1 GEMM (bn2+leaky fused), W duplicated in smem, natural b-pairs ----------------
// block: (jb 0..7, sp 0..63). 64 j x 64 b; one channel (576 k) per sp, staged 32 kk at a time.
// thread: 8 j x 4 b. 128 threads.
__global__ void __launch_bounds__(128) k_fc1(const float* __restrict__ w,
                      const float* __restrict__ g2, const float* __restrict__ b2) {
    __shared__ __align__(16) float Ws[32][132];   // [kk][2*j dup]
    __shared__ __align__(16) float Xs[32][66];    // [kk][b]
    const int jb = blockIdx.x, sp = blockIdx.y;
    const int t = threadIdx.x;

    // BN coefficients for the single channel this block covers (c == sp)
    float s = 0.f, q = 0.f;
    #pragma unroll
    for (int i = 0; i < 8; i++) { s += g_s2p[i][sp]; q += g_q2p[i][sp]; }
    const float n = (float)(BATCH * H2 * H2);
    const float m = s / n;
    const float var = q / n - m * m;
    const float sc = rsqrtf(var + EPSV) * g2[sp];
    const float sh = b2[sp] - m * sc;

    const int j0 = (t & 7) * 8;      // 8 j per thread
    const int b0 = (t >> 3) * 4;     // 4 b per thread
    u64 acc[8][2];
    #pragma unroll
    for (int jj = 0; jj < 8; jj++) { acc[jj][0] = 0ull; acc[jj][1] = 0ull; }

    for (int ch = 0; ch < 18; ch++) {
        const int k0 = sp * 576 + ch * 32;
        __syncthreads();
        #pragma unroll
        for (int rep = 0; rep < 4; rep++) {          // W: 64 j x 8 float4-of-k
            int task = rep * 128 + t;
            int kc = task & 7, jj = task >> 3;
            float4 v = *(const float4*)&w[(jb * 64 + jj) * NFC + k0 + kc * 4];
            *(float2*)&Ws[kc * 4 + 0][2 * jj] = make_float2(v.x, v.x);
            *(float2*)&Ws[kc * 4 + 1][2 * jj] = make_float2(v.y, v.y);
            *(float2*)&Ws[kc * 4 + 2][2 * jj] = make_float2(v.z, v.z);
            *(float2*)&Ws[kc * 4 + 3][2 * jj] = make_float2(v.w, v.w);
        }
        #pragma unroll
        for (int rep = 0; rep < 4; rep++) {          // X: 64 b x 8 float4-of-k
            int task = rep * 128 + t;
            int kc = task & 7, bb = task >> 3;
            float4 v = *(const float4*)&g_conv2[bb * NFC + k0 + kc * 4];
            float a0 = v.x * sc + sh; a0 = a0 > 0.f ? a0 : 0.2f * a0;
            float a1 = v.y * sc + sh; a1 = a1 > 0.f ? a1 : 0.2f * a1;
            float a2 = v.z * sc + sh; a2 = a2 > 0.f ? a2 : 0.2f * a2;
            float a3 = v.w * sc + sh; a3 = a3 > 0.f ? a3 : 0.2f * a3;
            Xs[kc * 4 + 0][bb] = a0;
            Xs[kc * 4 + 1][bb] = a1;
            Xs[kc * 4 + 2][bb] = a2;
            Xs[kc * 4 + 3][bb] = a3;
        }
        __syncthreads();
        #pragma unroll 8
        for (int kk = 0; kk < 32; kk++) {
            ulonglong2 wa = *(const ulonglong2*)&Ws[kk][2 * j0];
            ulonglong2 wb = *(const ulonglong2*)&Ws[kk][2 * j0 + 4];
            ulonglong2 wc = *(const ulonglong2*)&Ws[kk][2 * j0 + 8];
            ulonglong2 wd = *(const ulonglong2*)&Ws[kk][2 * j0 + 12];
            u64 x0 = *(const u64*)&Xs[kk][b0];
            u64 x1 = *(const u64*)&Xs[kk][b0 + 2];
            fma2(acc[0][0], wa.x, x0); fma2(acc[0][1], wa.x, x1);
            fma2(acc[1][0], wa.y, x0); fma2(acc[1][1], wa.y, x1);
            fma2(acc[2][0], wb.x, x0); fma2(acc[2][1], wb.x, x1);
            fma2(acc[3][0], wb.y, x0); fma2(acc[3][1], wb.y, x1);
            fma2(acc[4][0], wc.x, x0); fma2(acc[4][1], wc.x, x1);
            fma2(acc[5][0], wc.y, x0); fma2(acc[5][1], wc.y, x1);
            fma2(acc[6][0], wd.x, x0); fma2(acc[6][1], wd.x, x1);
            fma2(acc[7][0], wd.y, x0); fma2(acc[7][1], wd.y, x1);
        }
    }
    #pragma unroll
    for (int jj = 0; jj < 8; jj++) {
        int j = jb * 64 + j0 + jj;
        #pragma unroll
        for (int bp = 0; bp < 2; bp++) {
            float2 v = unpk(acc[jj][bp]);
            g_part[(sp * BATCH + b0 + 2 * bp)     * NJ + j] = v.x;
            g_part[(sp * BATCH + b0 + 2 * bp + 1) * NJ + j] = v.y;
        }
    }
}

// ---------------- K7: reduce split-K partials + fc1 bias ----------------
__global__ void k_redpart(const float* __restrict__ fc1b) {
    const int b = blockIdx.x, j = threadIdx.x;
    float y = fc1b[j];
    #pragma unroll 8
    for (int s = 0; s < NSPLIT; s++) y += g_part[(s * BATCH + b) * NJ + j];
    g_ybuf[b * NJ + j] = y;
}

// ---------------- K8: bn3 + leaky + fc2 + sigmoid ----------------
__global__ void k_final(const float* __restrict__ g3, const float* __restrict__ b3,
                        const float* __restrict__ w2, const float* __restrict__ bias2,
                        float* __restrict__ out) {
    __shared__ float sc[NJ], sh[NJ], w2s[NJ];
    const int t = threadIdx.x;
    float s = 0.f, ss = 0.f;
    for (int b = 0; b < BATCH; b++) {
        float v = g_ybuf[b * NJ + t];
        s += v; ss += v * v;
    }
    float m = s * (1.f / BATCH);
    float var = ss * (1.f / BATCH) - m * m;
    float scale = rsqrtf(var + EPSV) * g3[t];
    sc[t] = scale; sh[t] = b3[t] - m * scale; w2s[t] = w2[t];
    __syncthreads();
    const int warp = t / 32, lane = t % 32;
    for (int b = warp * 4; b < warp * 4 + 4; b++) {
        float p = 0.f;
        for (int j = lane; j < NJ; j += 32) {
            float v = g_ybuf[b * NJ + j] * sc[j] + sh[j];
            v = v > 0.f ? v : 0.2f * v;
            p += v * w2s[j];
        }
        #pragma unroll
        for (int off = 16; off > 0; off >>= 1)
            p += __shfl_down_sync(0xffffffffu, p, off);
        if (lane == 0) out[b] = 1.f / (1.f + expf(-(p + bias2[0])));
    }
}

// ---------------- launch ----------------
extern "C" void kernel_launch(void* const* d_in, const int* in_sizes, int n_in,
                              void* d_out, int out_size) {
    (void)in_sizes; (void)n_in; (void)out_size;
    const float* image = (const float*)d_in[0];
    const float* c1w = (const float*)d_in[1];
    const float* c1b = (const float*)d_in[2];
    const float* g1  = (const float*)d_in[3];
    const float* b1  = (const float*)d_in[4];
    const float* c2w = (const float*)d_in[5];
    const float* c2b = (const float*)d_in[6];
    const float* g2  = (const float*)d_in[7];
    const float* b2  = (const float*)d_in[8];
    const float* fw1 = (const float*)d_in[9];
    const float* fb1 = (const float*)d_in[10];
    const float* g3  = (const float*)d_in[11];
    const float* b3  = (const float*)d_in[12];
    const float* fw2 = (const float*)d_in[13];
    const float* fb2 = (const float*)d_in[14];
    float* out = (float*)d_out;

    k_wt     <<<222, 256>>>(c1w, c2w);
    k_layout <<<dim3(46, 64), 256>>>(image);
    k_conv1  <<<dim3(5, 7, 64), 256>>>(c1b);
    k_red1   <<<dim3(OC1, 8), 256>>>();
    k_conv2  <<<dim3(3, 3, 64), 256>>>(c2b, g1, b1);
    k_red2   <<<dim3(OC2, 8), 256>>>();
    k_fc1    <<<dim3(8, NSPLIT), 128>>>(fw1, g2, b2);
    k_redpart<<<BATCH, NJ>>>(fb1);
    k_final  <<<1, NJ>>>(g3, b3, fw2, fb2, out);
}

// round 4
// speedup vs baseline: 1.4677x; 1.4677x over previous
#include <cuda_runtime.h>
#include <math.h>

#define BATCH 64
#define NOBJ  16
#define NCLS  7
#define HWDIM 108
#define H1    52
#define OC1   32
#define H2    24
#define OC2   64
#define NFC   36864      // OC2 * H2 * H2
#define NJ    512
#define NSPLIT 32
#define CHUNK  1152      // NFC / NSPLIT (= 2 channels of 576)
#define EPSV  1e-5f

typedef unsigned long long u64;

__device__ __forceinline__ void fma2(u64& d, u64 a, u64 b) {
    asm("fma.rn.f32x2 %0, %1, %2, %0;" : "+l"(d) : "l"(a), "l"(b));
}
__device__ __forceinline__ u64 dup2(float v) {
    u64 d; asm("mov.b64 %0, {%1, %1};" : "=l"(d) : "f"(v)); return d;
}
__device__ __forceinline__ float2 unpk(u64 v) {
    float2 r; asm("mov.b64 {%0, %1}, %2;" : "=f"(r.x), "=f"(r.y) : "l"(v)); return r;
}

// ---------------- scratch (device globals; no allocation) ----------------
__device__ float g_layout[BATCH * NCLS * HWDIM * HWDIM];
__device__ float g_conv1 [BATCH * OC1 * H1 * H1];
__device__ float g_conv2 [BATCH * OC2 * H2 * H2];
__device__ float g_part  [NSPLIT * BATCH * NJ];
__device__ float g_ybuf  [BATCH * NJ];
__device__ float g_s1p[8][OC1], g_q1p[8][OC1];
__device__ float g_s2p[8][OC2], g_q2p[8][OC2];
__device__ float g_w1t[NCLS * 25 * OC1];   // [ic*25+k][oc]
__device__ float g_w2t[OC1 * 25 * OC2];    // [ic*25+k][oc]

// ---------------- weight transpose prep ----------------
__global__ void k_wt(const float* __restrict__ w1, const float* __restrict__ w2) {
    int i = blockIdx.x * 256 + threadIdx.x;
    if (i < NCLS * 25 * OC1) {
        int kic = i / OC1, oc = i % OC1;
        g_w1t[i] = w1[oc * 175 + kic];
    }
    int j = i - NCLS * 25 * OC1;
    if (j >= 0 && j < OC1 * 25 * OC2) {
        int kic = j / OC2, oc = j % OC2;
        g_w2t[j] = w2[oc * 800 + kic];
    }
}

// ---------------- K1: layout_bbox + transpose to NCHW ----------------
__global__ void k_layout(const float* __restrict__ image) {
    __shared__ float sx1[NOBJ], sx2[NOBJ], sy1[NOBJ], sy2[NOBJ];
    __shared__ float scls[NOBJ][NCLS];
    const int b = blockIdx.y;
    const int t = threadIdx.x;
    if (t < NOBJ) {
        const float* p = image + (b * NOBJ + t) * (4 + NCLS);
        float xc = p[0] * 108.f, yc = p[1] * 108.f;
        float w  = p[2] * 108.f, h  = p[3] * 108.f;
        sx1[t] = xc - 0.5f * w; sx2[t] = xc + 0.5f * w;
        sy1[t] = yc - 0.5f * h; sy2[t] = yc + 0.5f * h;
        #pragma unroll
        for (int c = 0; c < NCLS; c++) scls[t][c] = p[4 + c];
    }
    __syncthreads();
    const int pix = blockIdx.x * 256 + t;
    if (pix >= HWDIM * HWDIM) return;
    const int hh = pix / HWDIM, ww = pix % HWDIM;
    const float yt = (float)hh, xt = (float)ww;
    float acc[NCLS];
    #pragma unroll
    for (int c = 0; c < NCLS; c++) acc[c] = -1e30f;
    for (int o = 0; o < NOBJ; o++) {
        float x1d = xt - sx1[o], x2d = sx2[o] - xt;
        float y1d = yt - sy1[o], y2d = sy2[o] - yt;
        float yband = fminf(fmaxf(y1d, 0.f), 1.f) * fminf(fmaxf(y2d, 0.f), 1.f);
        float xband = fminf(fmaxf(x1d, 0.f), 1.f) * fminf(fmaxf(x2d, 0.f), 1.f);
        float l1 = fmaxf(1.f - fabsf(x1d), 0.f) * yband;
        float l2 = fmaxf(1.f - fabsf(x2d), 0.f) * yband;
        float l3 = fmaxf(1.f - fabsf(y1d), 0.f) * xband;
        float l4 = fmaxf(1.f - fabsf(y2d), 0.f) * xband;
        float m = fmaxf(fmaxf(l1, l2), fmaxf(l3, l4));
        #pragma unroll
        for (int c = 0; c < NCLS; c++) acc[c] = fmaxf(acc[c], m * scls[o][c]);
    }
    #pragma unroll
    for (int c = 0; c < NCLS; c++)
        g_layout[((b * NCLS + c) * HWDIM + hh) * HWDIM + ww] = acc[c];
}

// ---------------- K2: conv1 7->32, 5x5 stride 2, register-packed f32x2 ----------------
// block: (xtile 0..4, ytile 0..6, b). out tile 8 rows x 12 cols, all 32 oc. 256 threads.
// thread: 4 oc (2 pairs) x 3 consecutive ow.
__global__ void __launch_bounds__(256, 4) k_conv1(const float* __restrict__ bias) {
    __shared__ float xs[NCLS][19][28];
    __shared__ __align__(16) float ws[175 * OC1];
    const int b   = blockIdx.z;
    const int oh0 = blockIdx.y * 8;
    const int ow0 = blockIdx.x * 12;
    const int t   = threadIdx.x;

    for (int i = t; i < NCLS * 19 * 28; i += 256) {
        int ic  = i / (19 * 28);
        int rem = i % (19 * 28);
        int rr = rem / 28, cc = rem % 28;
        int row = 2 * oh0 + rr, col = 2 * ow0 + cc;
        float v = 0.f;
        if (cc < 27 && row < HWDIM && col < HWDIM)
            v = g_layout[((b * NCLS + ic) * HWDIM + row) * HWDIM + col];
        xs[ic][rr][cc] = v;
    }
    for (int i = t; i < 175 * OC1 / 4; i += 256)
        ((float4*)ws)[i] = ((const float4*)g_w1t)[i];
    __syncthreads();

    const int oc0 = (t & 7) * 4;
    const int pg  = t >> 3;          // 0..31
    const int r   = pg >> 2;         // 0..7
    const int c0  = (pg & 3) * 3;    // 0,3,6,9

    u64 acc[2][3];
    #pragma unroll
    for (int q = 0; q < 2; q++)
        #pragma unroll
        for (int p = 0; p < 3; p++) acc[q][p] = 0ull;

    for (int ic = 0; ic < NCLS; ic++) {
        #pragma unroll
        for (int ky = 0; ky < 5; ky++) {
            const float* xr = &xs[ic][2 * r + ky][2 * c0];
            u64 xe[5];
            #pragma unroll
            for (int m = 0; m < 5; m++) xe[m] = dup2(xr[2 * m]);
            #pragma unroll
            for (int kh = 0; kh < 3; kh++) {          // kx = 0,2,4
                ulonglong2 wq = *(const ulonglong2*)&ws[(ic * 25 + ky * 5 + 2 * kh) * OC1 + oc0];
                #pragma unroll
                for (int p = 0; p < 3; p++) {
                    fma2(acc[0][p], wq.x, xe[kh + p]);
                    fma2(acc[1][p], wq.y, xe[kh + p]);
                }
            }
            u64 xo[4];
            #pragma unroll
            for (int m = 0; m < 4; m++) xo[m] = dup2(xr[2 * m + 1]);
            #pragma unroll
            for (int kh = 0; kh < 2; kh++) {          // kx = 1,3
                ulonglong2 wq = *(const ulonglong2*)&ws[(ic * 25 + ky * 5 + 2 * kh + 1) * OC1 + oc0];
                #pragma unroll
                for (int p = 0; p < 3; p++) {
                    fma2(acc[0][p], wq.x, xo[kh + p]);
                    fma2(acc[1][p], wq.y, xo[kh + p]);
                }
            }
        }
    }
    const int oh = oh0 + r;
    if (oh < H1) {
        #pragma unroll
        for (int q = 0; q < 2; q++) {
            float ba = bias[oc0 + 2 * q], bb = bias[oc0 + 2 * q + 1];
            #pragma unroll
            for (int p = 0; p < 3; p++) {
                int ow = ow0 + c0 + p;
                if (ow < H1) {
                    float2 v = unpk(acc[q][p]);
                    g_conv1[((b * OC1 + oc0 + 2 * q)     * H1 + oh) * H1 + ow] = v.x + ba;
                    g_conv1[((b * OC1 + oc0 + 2 * q + 1) * H1 + oh) * H1 + ow] = v.y + bb;
                }
            }
        }
    }
}

// ---------------- K3/K5: two-stage deterministic per-channel sum/sumsq ----------------
__global__ void k_red1() {
    const int c = blockIdx.x, bg = blockIdx.y, t = threadIdx.x;
    float s = 0.f, ss = 0.f;
    for (int i = t; i < 8 * 676; i += 256) {
        int b = bg * 8 + i / 676;
        float4 v = *(const float4*)&g_conv1[(b * OC1 + c) * 2704 + (i % 676) * 4];
        s  += (v.x + v.y) + (v.z + v.w);
        ss += (v.x * v.x + v.y * v.y) + (v.z * v.z + v.w * v.w);
    }
    __shared__ float rs[256], rq[256];
    rs[t] = s; rq[t] = ss;
    __syncthreads();
    for (int off = 128; off > 0; off >>= 1) {
        if (t < off) { rs[t] += rs[t + off]; rq[t] += rq[t + off]; }
        __syncthreads();
    }
    if (t == 0) { g_s1p[bg][c] = rs[0]; g_q1p[bg][c] = rq[0]; }
}

__global__ void k_red2() {
    const int c = blockIdx.x, bg = blockIdx.y, t = threadIdx.x;
    float s = 0.f, ss = 0.f;
    for (int i = t; i < 8 * 144; i += 256) {
        int b = bg * 8 + i / 144;
        float4 v = *(const float4*)&g_conv2[(b * OC2 + c) * 576 + (i % 144) * 4];
        s  += (v.x + v.y) + (v.z + v.w);
        ss += (v.x * v.x + v.y * v.y) + (v.z * v.z + v.w * v.w);
    }
    __shared__ float rs[256], rq[256];
    rs[t] = s; rq[t] = ss;
    __syncthreads();
    for (int off = 128; off > 0; off >>= 1) {
        if (t < off) { rs[t] += rs[t + off]; rq[t] += rq[t + off]; }
        __syncthreads();
    }
    if (t == 0) { g_s2p[bg][c] = rs[0]; g_q2p[bg][c] = rq[0]; }
}

// ---------------- K4: bn1+leaky fused into conv2 32->64, f32x2 packed (R2 version) ----------------
// block: (xtile 0..2, ytile 0..2, b). out tile 8x8, 64 oc. 128 threads.
// thread: 4 oc (2 pairs) x 8 ow (full row).
__global__ void __launch_bounds__(128) k_conv2(const float* __restrict__ bias,
                        const float* __restrict__ g1, const float* __restrict__ b1) {
    __shared__ __align__(16) float xsd[4][19][40];
    __shared__ __align__(16) float ws[100 * OC2];
    __shared__ float sc1[OC1], sh1[OC1];
    const int b   = blockIdx.z;
    const int oh0 = blockIdx.y * 8;
    const int ow0 = blockIdx.x * 8;
    const int t   = threadIdx.x;

    if (t < OC1) {
        float s = 0.f, q = 0.f;
        #pragma unroll
        for (int i = 0; i < 8; i++) { s += g_s1p[i][t]; q += g_q1p[i][t]; }
        float n = (float)(BATCH * H1 * H1);
        float m = s / n;
        float v = q / n - m * m;
        float sc = rsqrtf(v + EPSV) * g1[t];
        sc1[t] = sc; sh1[t] = b1[t] - m * sc;
    }

    const int oc0 = (t & 15) * 4;
    const int r   = t >> 4;          // 0..7

    u64 acc[2][8];
    #pragma unroll
    for (int q = 0; q < 2; q++)
        #pragma unroll
        for (int p = 0; p < 8; p++) acc[q][p] = 0ull;

    for (int icb = 0; icb < OC1; icb += 4) {
        __syncthreads();
        for (int i = t; i < 4 * 19 * 19; i += 128) {
            int i2  = i / 361;
            int rem = i % 361;
            int rr = rem / 19, cc = rem % 19;
            int ic = icb + i2;
            float v = g_conv1[((b * OC1 + ic) * H1 + 2 * oh0 + rr) * H1 + 2 * ow0 + cc];
            v = v * sc1[ic] + sh1[ic];
            v = v > 0.f ? v : 0.2f * v;
            *(float2*)&xsd[i2][rr][2 * cc] = make_float2(v, v);
        }
        const float4* src = (const float4*)(g_w2t + icb * 25 * OC2);
        for (int i = t; i < 100 * OC2 / 4; i += 128)
            ((float4*)ws)[i] = src[i];
        __syncthreads();

        #pragma unroll
        for (int i2 = 0; i2 < 4; i2++) {
            #pragma unroll
            for (int ky = 0; ky < 5; ky++) {
                const float* xrow = xsd[i2][2 * r + ky];
                {   // positions 0..3 use x[0..10]
                    u64 xd[11];
                    #pragma unroll
                    for (int u = 0; u < 11; u++) xd[u] = *(const u64*)(xrow + 2 * u);
                    #pragma unroll
                    for (int kx = 0; kx < 5; kx++) {
                        ulonglong2 wq = *(const ulonglong2*)&ws[(i2 * 25 + ky * 5 + kx) * OC2 + oc0];
                        #pragma unroll
                        for (int p = 0; p < 4; p++) {
                            fma2(acc[0][p], wq.x, xd[2 * p + kx]);
                            fma2(acc[1][p], wq.y, xd[2 * p + kx]);
                        }
                    }
                }
                {   // positions 4..7 use x[8..18]
                    u64 xd[11];
                    #pragma unroll
                    for (int u = 0; u < 11; u++) xd[u] = *(const u64*)(xrow + 2 * (8 + u));
                    #pragma unroll
                    for (int kx = 0; kx < 5; kx++) {
                        ulonglong2 wq = *(const ulonglong2*)&ws[(i2 * 25 + ky * 5 + kx) * OC2 + oc0];
                        #pragma unroll
                        for (int p = 4; p < 8; p++) {
                            fma2(acc[0][p], wq.x, xd[2 * (p - 4) + kx]);
                            fma2(acc[1][p], wq.y, xd[2 * (p - 4) + kx]);
                        }
                    }
                }
            }
        }
    }
    const int oh = oh0 + r;
    #pragma unroll
    for (int q = 0; q < 2; q++) {
        float ba = bias[oc0 + 2 * q], bb = bias[oc0 + 2 * q + 1];
        #pragma unroll
        for (int p = 0; p < 8; p++) {
            int ow = ow0 + p;
            float2 v = unpk(acc[q][p]);
            g_conv2[((b * OC2 + oc0 + 2 * q)     * H2 + oh) * H2 + ow] = v.x + ba;
            g_conv2[((b * OC2 + oc0 + 2 * q + 1) * H2 + oh) * H2 + ow] = v.y + bb;
        }
    }
}

// ---------------- K6: fc1 GEMM (bn2+leaky fused), split-K, f32x2 packed (R2 version) ----------------
// block: (jb 0..15, sp 0..31). 32 j x 64 b; K chunk 64. 128 threads, thread 4j x 4b.
__global__ void __launch_bounds__(128) k_fc1(const float* __restrict__ w,
                      const float* __restrict__ g2, const float* __restrict__ b2) {
    __shared__ __align__(16) float Xsd[64][134];   // [kk][b duplicated]
    __shared__ __align__(16) float Ws[64][36];     // [kk][jj]
    __shared__ float sc2[OC2], sh2[OC2];
    const int jb = blockIdx.x, sp = blockIdx.y;
    const int t = threadIdx.x;

    if (t < OC2) {
        float s = 0.f, q = 0.f;
        #pragma unroll
        for (int i = 0; i < 8; i++) { s += g_s2p[i][t]; q += g_q2p[i][t]; }
        float n = (float)(BATCH * H2 * H2);
        float m = s / n;
        float v = q / n - m * m;
        float sc = rsqrtf(v + EPSV) * g2[t];
        sc2[t] = sc; sh2[t] = b2[t] - m * sc;
    }

    const int j0 = (t & 7) * 4;
    const int b0 = (t >> 3) * 4;
    u64 acc[2][4];
    #pragma unroll
    for (int q = 0; q < 2; q++)
        #pragma unroll
        for (int p = 0; p < 4; p++) acc[q][p] = 0ull;

    const int base = sp * CHUNK;
    for (int ch = 0; ch < CHUNK / 64; ch++) {
        const int k0 = base + ch * 64;
        const int c = k0 / 576;     // 64-blocks never cross a channel boundary
        __syncthreads();
        const float sc = sc2[c], sh = sh2[c];
        for (int i = t; i < 512; i += 128) {
            int jj = i >> 4, k4 = (i & 15) * 4;
            float4 v = *(const float4*)&w[(jb * 32 + jj) * NFC + k0 + k4];
            Ws[k4][jj] = v.x; Ws[k4 + 1][jj] = v.y; Ws[k4 + 2][jj] = v.z; Ws[k4 + 3][jj] = v.w;
        }
        for (int i = t; i < 1024; i += 128) {
            int bb = i >> 4, k4 = (i & 15) * 4;
            float4 v = *(const float4*)&g_conv2[bb * NFC + k0 + k4];
            float a0 = v.x * sc + sh; a0 = a0 > 0.f ? a0 : 0.2f * a0;
            float a1 = v.y * sc + sh; a1 = a1 > 0.f ? a1 : 0.2f * a1;
            float a2 = v.z * sc + sh; a2 = a2 > 0.f ? a2 : 0.2f * a2;
            float a3 = v.w * sc + sh; a3 = a3 > 0.f ? a3 : 0.2f * a3;
            *(float2*)&Xsd[k4][2 * bb]     = make_float2(a0, a0);
            *(float2*)&Xsd[k4 + 1][2 * bb] = make_float2(a1, a1);
            *(float2*)&Xsd[k4 + 2][2 * bb] = make_float2(a2, a2);
            *(float2*)&Xsd[k4 + 3][2 * bb] = make_float2(a3, a3);
        }
        __syncthreads();
        #pragma unroll 8
        for (int kk = 0; kk < 64; kk++) {
            ulonglong2 wq = *(const ulonglong2*)&Ws[kk][j0];
            #pragma unroll
            for (int p = 0; p < 4; p++) {
                u64 xv = *(const u64*)&Xsd[kk][2 * (b0 + p)];
                fma2(acc[0][p], wq.x, xv);
                fma2(acc[1][p], wq.y, xv);
            }
        }
    }
    #pragma unroll
    for (int p = 0; p < 4; p++) {
        float2 v0 = unpk(acc[0][p]), v1 = unpk(acc[1][p]);
        float* dst = &g_part[(sp * BATCH + b0 + p) * NJ + jb * 32 + j0];
        dst[0] = v0.x; dst[1] = v0.y; dst[2] = v1.x; dst[3] = v1.y;
    }
}

// ---------------- K7: reduce split-K partials + fc1 bias ----------------
__global__ void k_redpart(const float* __restrict__ fc1b) {
    const int b = blockIdx.x, j = threadIdx.x;
    float y = fc1b[j];
    #pragma unroll
    for (int s = 0; s < NSPLIT; s++) y += g_part[(s * BATCH + b) * NJ + j];
    g_ybuf[b * NJ + j] = y;
}

// ---------------- K8: bn3 + leaky + fc2 + sigmoid ----------------
__global__ void k_final(const float* __restrict__ g3, const float* __restrict__ b3,
                        const float* __restrict__ w2, const float* __restrict__ bias2,
                        float* __restrict__ out) {
    __shared__ float sc[NJ], sh[NJ], w2s[NJ];
    const int t = threadIdx.x;
    float s = 0.f, ss = 0.f;
    for (int b = 0; b < BATCH; b++) {
        float v = g_ybuf[b * NJ + t];
        s += v; ss += v * v;
    }
    float m = s * (1.f / BATCH);
    float var = ss * (1.f / BATCH) - m * m;
    float scale = rsqrtf(var + EPSV) * g3[t];
    sc[t] = scale; sh[t] = b3[t] - m * scale; w2s[t] = w2[t];
    __syncthreads();
    const int warp = t / 32, lane = t % 32;
    for (int b = warp * 4; b < warp * 4 + 4; b++) {
        float p = 0.f;
        for (int j = lane; j < NJ; j += 32) {
            float v = g_ybuf[b * NJ + j] * sc[j] + sh[j];
            v = v > 0.f ? v : 0.2f * v;
            p += v * w2s[j];
        }
        #pragma unroll
        for (int off = 16; off > 0; off >>= 1)
            p += __shfl_down_sync(0xffffffffu, p, off);
        if (lane == 0) out[b] = 1.f / (1.f + expf(-(p + bias2[0])));
    }
}

// ---------------- launch ----------------
extern "C" void kernel_launch(void* const* d_in, const int* in_sizes, int n_in,
                              void* d_out, int out_size) {
    (void)in_sizes; (void)n_in; (void)out_size;
    const float* image = (const float*)d_in[0];
    const float* c1w = (const float*)d_in[1];
    const float* c1b = (const float*)d_in[2];
    const float* g1  = (const float*)d_in[3];
    const float* b1  = (const float*)d_in[4];
    const float* c2w = (const float*)d_in[5];
    const float* c2b = (const float*)d_in[6];
    const float* g2  = (const float*)d_in[7];
    const float* b2  = (const float*)d_in[8];
    const float* fw1 = (const float*)d_in[9];
    const float* fb1 = (const float*)d_in[10];
    const float* g3  = (const float*)d_in[11];
    const float* b3  = (const float*)d_in[12];
    const float* fw2 = (const float*)d_in[13];
    const float* fb2 = (const float*)d_in[14];
    float* out = (float*)d_out;

    k_wt     <<<222, 256>>>(c1w, c2w);
    k_layout <<<dim3(46, 64), 256>>>(image);
    k_conv1  <<<dim3(5, 7, 64), 256>>>(c1b);
    k_red1   <<<dim3(OC1, 8), 256>>>();
    k_conv2  <<<dim3(3, 3, 64), 128>>>(c2b, g1, b1);
    k_red2   <<<dim3(OC2, 8), 256>>>();
    k_fc1    <<<dim3(16, NSPLIT), 128>>>(fw1, g2, b2);
    k_redpart<<<BATCH, NJ>>>(fb1);
    k_final  <<<1, NJ>>>(g3, b3, fw2, fb2, out);
}

// round 6
// speedup vs baseline: 1.9500x; 1.3286x over previous
#include <cuda_runtime.h>
#include <math.h>
#include <stdint.h>

#define BATCH 64
#define NOBJ  16
#define NCLS  7
#define HWDIM 108
#define H1    52
#define OC1   32
#define H2    24
#define OC2   64
#define NFC   36864      // OC2 * H2 * H2
#define NJ    512
#define NSPLIT 32
#define EPSV  1e-5f

typedef unsigned long long u64;

__device__ __forceinline__ void fma2(u64& d, u64 a, u64 b) {
    asm("fma.rn.f32x2 %0, %1, %2, %0;" : "+l"(d) : "l"(a), "l"(b));
}
__device__ __forceinline__ u64 dup2(float v) {
    u64 d; asm("mov.b64 %0, {%1, %1};" : "=l"(d) : "f"(v)); return d;
}
__device__ __forceinline__ float2 unpk(u64 v) {
    float2 r; asm("mov.b64 {%0, %1}, %2;" : "=f"(r.x), "=f"(r.y) : "l"(v)); return r;
}

// mma.sync m16n8k8 tf32 (HMMA, available on plain sm_103 target)
__device__ __forceinline__ void mma_tf32(float& c0, float& c1, float& c2, float& c3,
                                         uint32_t a0, uint32_t a1, uint32_t a2, uint32_t a3,
                                         uint32_t b0, uint32_t b1) {
    asm volatile(
        "mma.sync.aligned.m16n8k8.row.col.f32.tf32.tf32.f32 "
        "{%0,%1,%2,%3}, {%4,%5,%6,%7}, {%8,%9}, {%0,%1,%2,%3};"
        : "+f"(c0), "+f"(c1), "+f"(c2), "+f"(c3)
        : "r"(a0), "r"(a1), "r"(a2), "r"(a3), "r"(b0), "r"(b1));
}

// ---------------- scratch (device globals; no allocation) ----------------
__device__ float g_layout[BATCH * NCLS * HWDIM * HWDIM];
__device__ float g_conv1 [BATCH * OC1 * H1 * H1];
__device__ float g_conv2 [BATCH * OC2 * H2 * H2];
__device__ float g_part  [NSPLIT * BATCH * NJ];
__device__ float g_ybuf  [BATCH * NJ];
__device__ float g_s1p[8][OC1], g_q1p[8][OC1];
__device__ float g_s2p[8][OC2], g_q2p[8][OC2];
__device__ float g_w1t[NCLS * 25 * OC1];
__device__ float g_w2t[OC1 * 25 * OC2];

// ---------------- weight transpose prep ----------------
__global__ void k_wt(const float* __restrict__ w1, const float* __restrict__ w2) {
    int i = blockIdx.x * 256 + threadIdx.x;
    if (i < NCLS * 25 * OC1) {
        int kic = i / OC1, oc = i % OC1;
        g_w1t[i] = w1[oc * 175 + kic];
    }
    int j = i - NCLS * 25 * OC1;
    if (j >= 0 && j < OC1 * 25 * OC2) {
        int kic = j / OC2, oc = j % OC2;
        g_w2t[j] = w2[oc * 800 + kic];
    }
}

// ---------------- K1: layout_bbox + transpose to NCHW ----------------
__global__ void k_layout(const float* __restrict__ image) {
    __shared__ float sx1[NOBJ], sx2[NOBJ], sy1[NOBJ], sy2[NOBJ];
    __shared__ float scls[NOBJ][NCLS];
    const int b = blockIdx.y;
    const int t = threadIdx.x;
    if (t < NOBJ) {
        const float* p = image + (b * NOBJ + t) * (4 + NCLS);
        float xc = p[0] * 108.f, yc = p[1] * 108.f;
        float w  = p[2] * 108.f, h  = p[3] * 108.f;
        sx1[t] = xc - 0.5f * w; sx2[t] = xc + 0.5f * w;
        sy1[t] = yc - 0.5f * h; sy2[t] = yc + 0.5f * h;
        #pragma unroll
        for (int c = 0; c < NCLS; c++) scls[t][c] = p[4 + c];
    }
    __syncthreads();
    const int pix = blockIdx.x * 256 + t;
    if (pix >= HWDIM * HWDIM) return;
    const int hh = pix / HWDIM, ww = pix % HWDIM;
    const float yt = (float)hh, xt = (float)ww;
    float acc[NCLS];
    #pragma unroll
    for (int c = 0; c < NCLS; c++) acc[c] = -1e30f;
    for (int o = 0; o < NOBJ; o++) {
        float x1d = xt - sx1[o], x2d = sx2[o] - xt;
        float y1d = yt - sy1[o], y2d = sy2[o] - yt;
        float yband = fminf(fmaxf(y1d, 0.f), 1.f) * fminf(fmaxf(y2d, 0.f), 1.f);
        float xband = fminf(fmaxf(x1d, 0.f), 1.f) * fminf(fmaxf(x2d, 0.f), 1.f);
        float l1 = fmaxf(1.f - fabsf(x1d), 0.f) * yband;
        float l2 = fmaxf(1.f - fabsf(x2d), 0.f) * yband;
        float l3 = fmaxf(1.f - fabsf(y1d), 0.f) * xband;
        float l4 = fmaxf(1.f - fabsf(y2d), 0.f) * xband;
        float m = fmaxf(fmaxf(l1, l2), fmaxf(l3, l4));
        #pragma unroll
        for (int c = 0; c < NCLS; c++) acc[c] = fmaxf(acc[c], m * scls[o][c]);
    }
    #pragma unroll
    for (int c = 0; c < NCLS; c++)
        g_layout[((b * NCLS + c) * HWDIM + hh) * HWDIM + ww] = acc[c];
}

// ---------------- K2: conv1 (unchanged from R4) ----------------
__global__ void __launch_bounds__(256, 4) k_conv1(const float* __restrict__ bias) {
    __shared__ float xs[NCLS][19][28];
    __shared__ __align__(16) float ws[175 * OC1];
    const int b   = blockIdx.z;
    const int oh0 = blockIdx.y * 8;
    const int ow0 = blockIdx.x * 12;
    const int t   = threadIdx.x;

    for (int i = t; i < NCLS * 19 * 28; i += 256) {
        int ic  = i / (19 * 28);
        int rem = i % (19 * 28);
        int rr = rem / 28, cc = rem % 28;
        int row = 2 * oh0 + rr, col = 2 * ow0 + cc;
        float v = 0.f;
        if (cc < 27 && row < HWDIM && col < HWDIM)
            v = g_layout[((b * NCLS + ic) * HWDIM + row) * HWDIM + col];
        xs[ic][rr][cc] = v;
    }
    for (int i = t; i < 175 * OC1 / 4; i += 256)
        ((float4*)ws)[i] = ((const float4*)g_w1t)[i];
    __syncthreads();

    const int oc0 = (t & 7) * 4;
    const int pg  = t >> 3;
    const int r   = pg >> 2;
    const int c0  = (pg & 3) * 3;

    u64 acc[2][3];
    #pragma unroll
    for (int q = 0; q < 2; q++)
        #pragma unroll
        for (int p = 0; p < 3; p++) acc[q][p] = 0ull;

    for (int ic = 0; ic < NCLS; ic++) {
        #pragma unroll
        for (int ky = 0; ky < 5; ky++) {
            const float* xr = &xs[ic][2 * r + ky][2 * c0];
            u64 xe[5];
            #pragma unroll
            for (int m = 0; m < 5; m++) xe[m] = dup2(xr[2 * m]);
            #pragma unroll
            for (int kh = 0; kh < 3; kh++) {
                ulonglong2 wq = *(const ulonglong2*)&ws[(ic * 25 + ky * 5 + 2 * kh) * OC1 + oc0];
                #pragma unroll
                for (int p = 0; p < 3; p++) {
                    fma2(acc[0][p], wq.x, xe[kh + p]);
                    fma2(acc[1][p], wq.y, xe[kh + p]);
                }
            }
            u64 xo[4];
            #pragma unroll
            for (int m = 0; m < 4; m++) xo[m] = dup2(xr[2 * m + 1]);
            #pragma unroll
            for (int kh = 0; kh < 2; kh++) {
                ulonglong2 wq = *(const ulonglong2*)&ws[(ic * 25 + ky * 5 + 2 * kh + 1) * OC1 + oc0];
                #pragma unroll
                for (int p = 0; p < 3; p++) {
                    fma2(acc[0][p], wq.x, xo[kh + p]);
                    fma2(acc[1][p], wq.y, xo[kh + p]);
                }
            }
        }
    }
    const int oh = oh0 + r;
    if (oh < H1) {
        #pragma unroll
        for (int q = 0; q < 2; q++) {
            float ba = bias[oc0 + 2 * q], bb = bias[oc0 + 2 * q + 1];
            #pragma unroll
            for (int p = 0; p < 3; p++) {
                int ow = ow0 + c0 + p;
                if (ow < H1) {
                    float2 v = unpk(acc[q][p]);
                    g_conv1[((b * OC1 + oc0 + 2 * q)     * H1 + oh) * H1 + ow] = v.x + ba;
                    g_conv1[((b * OC1 + oc0 + 2 * q + 1) * H1 + oh) * H1 + ow] = v.y + bb;
                }
            }
        }
    }
}

// ---------------- K3/K5: reductions (unchanged) ----------------
__global__ void k_red1() {
    const int c = blockIdx.x, bg = blockIdx.y, t = threadIdx.x;
    float s = 0.f, ss = 0.f;
    for (int i = t; i < 8 * 676; i += 256) {
        int b = bg * 8 + i / 676;
        float4 v = *(const float4*)&g_conv1[(b * OC1 + c) * 2704 + (i % 676) * 4];
        s  += (v.x + v.y) + (v.z + v.w);
        ss += (v.x * v.x + v.y * v.y) + (v.z * v.z + v.w * v.w);
    }
    __shared__ float rs[256], rq[256];
    rs[t] = s; rq[t] = ss;
    __syncthreads();
    for (int off = 128; off > 0; off >>= 1) {
        if (t < off) { rs[t] += rs[t + off]; rq[t] += rq[t + off]; }
        __syncthreads();
    }
    if (t == 0) { g_s1p[bg][c] = rs[0]; g_q1p[bg][c] = rq[0]; }
}

__global__ void k_red2() {
    const int c = blockIdx.x, bg = blockIdx.y, t = threadIdx.x;
    float s = 0.f, ss = 0.f;
    for (int i = t; i < 8 * 144; i += 256) {
        int b = bg * 8 + i / 144;
        float4 v = *(const float4*)&g_conv2[(b * OC2 + c) * 576 + (i % 144) * 4];
        s  += (v.x + v.y) + (v.z + v.w);
        ss += (v.x * v.x + v.y * v.y) + (v.z * v.z + v.w * v.w);
    }
    __shared__ float rs[256], rq[256];
    rs[t] = s; rq[t] = ss;
    __syncthreads();
    for (int off = 128; off > 0; off >>= 1) {
        if (t < off) { rs[t] += rs[t + off]; rq[t] += rq[t + off]; }
        __syncthreads();
    }
    if (t == 0) { g_s2p[bg][c] = rs[0]; g_q2p[bg][c] = rq[0]; }
}

// ---------------- K4: conv2 (unchanged from R4) ----------------
__global__ void __launch_bounds__(128) k_conv2(const float* __restrict__ bias,
                        const float* __restrict__ g1, const float* __restrict__ b1) {
    __shared__ __align__(16) float xsd[4][19][40];
    __shared__ __align__(16) float ws[100 * OC2];
    __shared__ float sc1[OC1], sh1[OC1];
    const int b   = blockIdx.z;
    const int oh0 = blockIdx.y * 8;
    const int ow0 = blockIdx.x * 8;
    const int t   = threadIdx.x;

    if (t < OC1) {
        float s = 0.f, q = 0.f;
        #pragma unroll
        for (int i = 0; i < 8; i++) { s += g_s1p[i][t]; q += g_q1p[i][t]; }
        float n = (float)(BATCH * H1 * H1);
        float m = s / n;
        float v = q / n - m * m;
        float sc = rsqrtf(v + EPSV) * g1[t];
        sc1[t] = sc; sh1[t] = b1[t] - m * sc;
    }

    const int oc0 = (t & 15) * 4;
    const int r   = t >> 4;

    u64 acc[2][8];
    #pragma unroll
    for (int q = 0; q < 2; q++)
        #pragma unroll
        for (int p = 0; p < 8; p++) acc[q][p] = 0ull;

    for (int icb = 0; icb < OC1; icb += 4) {
        __syncthreads();
        for (int i = t; i < 4 * 19 * 19; i += 128) {
            int i2  = i / 361;
            int rem = i % 361;
            int rr = rem / 19, cc = rem % 19;
            int ic = icb + i2;
            float v = g_conv1[((b * OC1 + ic) * H1 + 2 * oh0 + rr) * H1 + 2 * ow0 + cc];
            v = v * sc1[ic] + sh1[ic];
            v = v > 0.f ? v : 0.2f * v;
            *(float2*)&xsd[i2][rr][2 * cc] = make_float2(v, v);
        }
        const float4* src = (const float4*)(g_w2t + icb * 25 * OC2);
        for (int i = t; i < 100 * OC2 / 4; i += 128)
            ((float4*)ws)[i] = src[i];
        __syncthreads();

        #pragma unroll
        for (int i2 = 0; i2 < 4; i2++) {
            #pragma unroll
            for (int ky = 0; ky < 5; ky++) {
                const float* xrow = xsd[i2][2 * r + ky];
                {
                    u64 xd[11];
                    #pragma unroll
                    for (int u = 0; u < 11; u++) xd[u] = *(const u64*)(xrow + 2 * u);
                    #pragma unroll
                    for (int kx = 0; kx < 5; kx++) {
                        ulonglong2 wq = *(const ulonglong2*)&ws[(i2 * 25 + ky * 5 + kx) * OC2 + oc0];
                        #pragma unroll
                        for (int p = 0; p < 4; p++) {
                            fma2(acc[0][p], wq.x, xd[2 * p + kx]);
                            fma2(acc[1][p], wq.y, xd[2 * p + kx]);
                        }
                    }
                }
                {
                    u64 xd[11];
                    #pragma unroll
                    for (int u = 0; u < 11; u++) xd[u] = *(const u64*)(xrow + 2 * (8 + u));
                    #pragma unroll
                    for (int kx = 0; kx < 5; kx++) {
                        ulonglong2 wq = *(const ulonglong2*)&ws[(i2 * 25 + ky * 5 + kx) * OC2 + oc0];
                        #pragma unroll
                        for (int p = 4; p < 8; p++) {
                            fma2(acc[0][p], wq.x, xd[2 * (p - 4) + kx]);
                            fma2(acc[1][p], wq.y, xd[2 * (p - 4) + kx]);
                        }
                    }
                }
            }
        }
    }
    const int oh = oh0 + r;
    #pragma unroll
    for (int q = 0; q < 2; q++) {
        float ba = bias[oc0 + 2 * q], bb = bias[oc0 + 2 * q + 1];
        #pragma unroll
        for (int p = 0; p < 8; p++) {
            int ow = ow0 + p;
            float2 v = unpk(acc[q][p]);
            g_conv2[((b * OC2 + oc0 + 2 * q)     * H2 + oh) * H2 + ow] = v.x + ba;
            g_conv2[((b * OC2 + oc0 + 2 * q + 1) * H2 + oh) * H2 + ow] = v.y + bb;
        }
    }
}

// ---------------- K6: fc1 via mma.sync tf32 (HMMA) ----------------
// grid (jb 0..7, sp 0..31): CTA computes D[64j x 64b] over K=1152 (2 channels).
// 256 threads = 8 warps; warp w: j-tile = (w&3)*16, b-tile = (w>>2)*32 (4 n-tiles of 8).
// smem stride 36 floats: bank = (4*row + k) % 32 -> conflict-free quad access.
__global__ void __launch_bounds__(256) k_fc1_mma(const float* __restrict__ w,
                      const float* __restrict__ g2, const float* __restrict__ b2) {
    __shared__ float smA[64 * 36];   // W tile  [j][k]
    __shared__ float smB[64 * 36];   // X tile  [b][k]
    const int jb = blockIdx.x, sp = blockIdx.y;
    const int t = threadIdx.x;
    const int wid = t >> 5, lane = t & 31;
    const int qrow = lane >> 2, qk = lane & 3;
    const int j0 = (wid & 3) * 16;
    const int b0 = (wid >> 2) * 32;

    // BN coeffs for the 2 channels this split covers
    const int c0 = 2 * sp;
    float scv[2], shv[2];
    #pragma unroll
    for (int ci = 0; ci < 2; ci++) {
        float s = 0.f, q = 0.f;
        #pragma unroll
        for (int i = 0; i < 8; i++) { s += g_s2p[i][c0 + ci]; q += g_q2p[i][c0 + ci]; }
        float n = (float)(BATCH * H2 * H2);
        float m = s / n;
        float var = q / n - m * m;
        float sc = rsqrtf(var + EPSV) * g2[c0 + ci];
        scv[ci] = sc; shv[ci] = b2[c0 + ci] - m * sc;
    }

    float c[4][4];
    #pragma unroll
    for (int nt = 0; nt < 4; nt++)
        #pragma unroll
        for (int i = 0; i < 4; i++) c[nt][i] = 0.f;

    const int kbase = sp * 1152;
    for (int ch = 0; ch < 36; ch++) {
        const int k0 = kbase + ch * 32;
        const float sc = scv[ch >= 18], sh = shv[ch >= 18];
        __syncthreads();
        // stage W: 64 rows x 8 float4
        #pragma unroll
        for (int rep = 0; rep < 2; rep++) {
            int idx = rep * 256 + t;
            int row = idx >> 3, kq = idx & 7;
            float4 v = *(const float4*)&w[(jb * 64 + row) * NFC + k0 + kq * 4];
            float* dst = &smA[row * 36 + kq * 4];
            dst[0] = v.x; dst[1] = v.y; dst[2] = v.z; dst[3] = v.w;
        }
        // stage X with BN+leaky: 64 rows x 8 float4
        #pragma unroll
        for (int rep = 0; rep < 2; rep++) {
            int idx = rep * 256 + t;
            int row = idx >> 3, kq = idx & 7;
            float4 v = *(const float4*)&g_conv2[row * NFC + k0 + kq * 4];
            v.x = v.x * sc + sh; v.x = v.x > 0.f ? v.x : 0.2f * v.x;
            v.y = v.y * sc + sh; v.y = v.y > 0.f ? v.y : 0.2f * v.y;
            v.z = v.z * sc + sh; v.z = v.z > 0.f ? v.z : 0.2f * v.z;
            v.w = v.w * sc + sh; v.w = v.w > 0.f ? v.w : 0.2f * v.w;
            float* dst = &smB[row * 36 + kq * 4];
            dst[0] = v.x; dst[1] = v.y; dst[2] = v.z; dst[3] = v.w;
        }
        __syncthreads();
        #pragma unroll
        for (int ks = 0; ks < 4; ks++) {
            const int kk = ks * 8;
            uint32_t a0 = __float_as_uint(smA[(j0 + qrow)     * 36 + kk + qk]);
            uint32_t a1 = __float_as_uint(smA[(j0 + qrow + 8) * 36 + kk + qk]);
            uint32_t a2 = __float_as_uint(smA[(j0 + qrow)     * 36 + kk + qk + 4]);
            uint32_t a3 = __float_as_uint(smA[(j0 + qrow + 8) * 36 + kk + qk + 4]);
            #pragma unroll
            for (int nt = 0; nt < 4; nt++) {
                uint32_t bb0 = __float_as_uint(smB[(b0 + nt * 8 + qrow) * 36 + kk + qk]);
                uint32_t bb1 = __float_as_uint(smB[(b0 + nt * 8 + qrow) * 36 + kk + qk + 4]);
                mma_tf32(c[nt][0], c[nt][1], c[nt][2], c[nt][3], a0, a1, a2, a3, bb0, bb1);
            }
        }
    }
    // epilogue: c0/c1 at (j = j0+qrow, b = nt*8 + 2*qk +0/1), c2/c3 at j+8
    const int jg = jb * 64 + j0 + qrow;
    #pragma unroll
    for (int nt = 0; nt < 4; nt++) {
        const int bcol = b0 + nt * 8 + 2 * qk;
        g_part[(sp * BATCH + bcol)     * NJ + jg]     = c[nt][0];
        g_part[(sp * BATCH + bcol + 1) * NJ + jg]     = c[nt][1];
        g_part[(sp * BATCH + bcol)     * NJ + jg + 8] = c[nt][2];
        g_part[(sp * BATCH + bcol + 1) * NJ + jg + 8] = c[nt][3];
    }
}

// ---------------- K7: reduce split-K partials + fc1 bias ----------------
__global__ void k_redpart(const float* __restrict__ fc1b) {
    const int b = blockIdx.x, j = threadIdx.x;
    float y = fc1b[j];
    #pragma unroll
    for (int s = 0; s < NSPLIT; s++) y += g_part[(s * BATCH + b) * NJ + j];
    g_ybuf[b * NJ + j] = y;
}

// ---------------- K8: bn3 + leaky + fc2 + sigmoid ----------------
__global__ void k_final(const float* __restrict__ g3, const float* __restrict__ b3,
                        const float* __restrict__ w2, const float* __restrict__ bias2,
                        float* __restrict__ out) {
    __shared__ float sc[NJ], sh[NJ], w2s[NJ];
    const int t = threadIdx.x;
    float s = 0.f, ss = 0.f;
    for (int b = 0; b < BATCH; b++) {
        float v = g_ybuf[b * NJ + t];
        s += v; ss += v * v;
    }
    float m = s * (1.f / BATCH);
    float var = ss * (1.f / BATCH) - m * m;
    float scale = rsqrtf(var + EPSV) * g3[t];
    sc[t] = scale; sh[t] = b3[t] - m * scale; w2s[t] = w2[t];
    __syncthreads();
    const int warp = t / 32, lane = t % 32;
    for (int b = warp * 4; b < warp * 4 + 4; b++) {
        float p = 0.f;
        for (int j = lane; j < NJ; j += 32) {
            float v = g_ybuf[b * NJ + j] * sc[j] + sh[j];
            v = v > 0.f ? v : 0.2f * v;
            p += v * w2s[j];
        }
        #pragma unroll
        for (int off = 16; off > 0; off >>= 1)
            p += __shfl_down_sync(0xffffffffu, p, off);
        if (lane == 0) out[b] = 1.f / (1.f + expf(-(p + bias2[0])));
    }
}

// ---------------- launch ----------------
extern "C" void kernel_launch(void* const* d_in, const int* in_sizes, int n_in,
                              void* d_out, int out_size) {
    (void)in_sizes; (void)n_in; (void)out_size;
    const float* image = (const float*)d_in[0];
    const float* c1w = (const float*)d_in[1];
    const float* c1b = (const float*)d_in[2];
    const float* g1  = (const float*)d_in[3];
    const float* b1  = (const float*)d_in[4];
    const float* c2w = (const float*)d_in[5];
    const float* c2b = (const float*)d_in[6];
    const float* g2  = (const float*)d_in[7];
    const float* b2  = (const float*)d_in[8];
    const float* fw1 = (const float*)d_in[9];
    const float* fb1 = (const float*)d_in[10];
    const float* g3  = (const float*)d_in[11];
    const float* b3  = (const float*)d_in[12];
    const float* fw2 = (const float*)d_in[13];
    const float* fb2 = (const float*)d_in[14];
    float* out = (float*)d_out;

    k_wt      <<<222, 256>>>(c1w, c2w);
    k_layout  <<<dim3(46, 64), 256>>>(image);
    k_conv1   <<<dim3(5, 7, 64), 256>>>(c1b);
    k_red1    <<<dim3(OC1, 8), 256>>>();
    k_conv2   <<<dim3(3, 3, 64), 128>>>(c2b, g1, b1);
    k_red2    <<<dim3(OC2, 8), 256>>>();
    k_fc1_mma <<<dim3(8, NSPLIT), 256>>>(fw1, g2, b2);
    k_redpart <<<BATCH, NJ>>>(fb1);
    k_final   <<<1, NJ>>>(g3, b3, fw2, fb2, out);
}